// round 4
// baseline (speedup 1.0000x reference)
#include <cuda_runtime.h>
#include <cstdint>

#define THREADS 512
#define VPT 16
#define NWARP (THREADS / 32)
#define FEAT 8192
#define CAP_EXIT 512

static_assert(THREADS * VPT == FEAT, "row must tile exactly");

// Monotonic uint key for fp32: key(x) = (u>>31) ? ~u : (u | 0x80000000).
// Inverse (pivot decode). Pivots landing in the negative-NaN code zone
// (keys < key(-inf) = 0x007FFFFF) are squashed to -inf so that float
// comparisons against the pivot match uint comparisons against the key
// for all finite data. Positive-NaN-zone pivots compare false for all x,
// which also matches the uint count (0) for finite data.
__device__ __forceinline__ float key_to_float(unsigned k) {
    unsigned u = (k & 0x80000000u) ? (k ^ 0x80000000u) : ~k;
    float f = __uint_as_float(u);
    if (k < 0x007FFFFFu) f = __uint_as_float(0xFF800000u);  // -inf
    return f;
}

__device__ __forceinline__ float warp_sum_f(float v) {
    #pragma unroll
    for (int o = 16; o > 0; o >>= 1) v += __shfl_xor_sync(0xFFFFFFFFu, v, o);
    return v;
}
__device__ __forceinline__ float warp_max_f(float v) {
    #pragma unroll
    for (int o = 16; o > 0; o >>= 1) v = fmaxf(v, __shfl_xor_sync(0xFFFFFFFFu, v, o));
    return v;
}

__global__ void __launch_bounds__(THREADS, 2)
rsoftmax_kernel(const float* __restrict__ in, const float* __restrict__ rate_p,
                float* __restrict__ out)
{
    __shared__ unsigned s_part[NWARP];
    __shared__ unsigned s_res;
    __shared__ float    s_partf[NWARP];
    __shared__ float    s_resf;
    __shared__ float    s_cand[CAP_EXIT];

    const int t    = threadIdx.x;
    const int lane = t & 31;
    const int wid  = t >> 5;
    const size_t row = blockIdx.x;
    const float4* rp = reinterpret_cast<const float4*>(in + row * FEAT);
    float4*       op = reinterpret_cast<float4*>(out + row * FEAT);

    // ---- load row into registers (fully coalesced float4) ----
    float x[VPT];
    #pragma unroll
    for (int i = 0; i < 4; i++) {
        float4 v = __ldg(rp + t + i * THREADS);
        x[4*i+0] = v.x; x[4*i+1] = v.y; x[4*i+2] = v.z; x[4*i+3] = v.w;
    }

    // ---- rank index from trainable scalar (device-resident) ----
    float rate = __ldg(rate_p);
    rate = fminf(fmaxf(rate, 0.0f), 1.0f);
    int idx = (int)(rate * (float)FEAT);       // truncation == astype(int32)
    if (idx > FEAT - 1) idx = FEAT - 1;        // jnp.take clip mode

    // ---- row max (needed for t_r, matches reference max_in) ----
    float mx = x[0];
    #pragma unroll
    for (int i = 1; i < VPT; i++) mx = fmaxf(mx, x[i]);
    mx = warp_max_f(mx);
    if (lane == 0) s_partf[wid] = mx;
    __syncthreads();
    if (wid == 0) {
        float v = (lane < NWARP) ? s_partf[lane] : __uint_as_float(0xFF800000u);
        v = warp_max_f(v);
        if (lane == 0) s_resf = v;
    }
    __syncthreads();
    mx = s_resf;

    // ---- phase 1: full-block bisection on key space ----
    // invariant: c(hi) <= idx < c(lo), where c(v) = #{x > v}
    unsigned lo = 0u, hi = 0xFFFFFFFFu;
    unsigned c_lo = FEAT, c_hi = 0u;
    while ((hi - lo) > 1u && (c_lo - c_hi) > CAP_EXIT) {
        unsigned mid = lo + ((hi - lo) >> 1);
        float piv = key_to_float(mid);
        unsigned c = 0;
        #pragma unroll
        for (int i = 0; i < VPT; i++) c += (x[i] > piv) ? 1u : 0u;
        c = __reduce_add_sync(0xFFFFFFFFu, c);
        if (lane == 0) s_part[wid] = c;
        __syncthreads();
        if (wid == 0) {
            unsigned v = (lane < NWARP) ? s_part[lane] : 0u;
            v = __reduce_add_sync(0xFFFFFFFFu, v);
            if (lane == 0) s_res = v;
        }
        __syncthreads();
        c = s_res;
        if (c <= (unsigned)idx) { hi = mid; c_hi = c; }
        else                    { lo = mid; c_lo = c; }
    }

    float thresh;
    if ((hi - lo) <= 1u) {
        thresh = key_to_float(hi);   // hi converged to the exact data key
    } else {
        // ---- phase 2: compact the <=512 in-range candidates (no atomics) ----
        float lof = key_to_float(lo), hif = key_to_float(hi);
        unsigned cm = 0;
        int cc = 0;
        #pragma unroll
        for (int i = 0; i < VPT; i++) {
            bool cnd = (x[i] > lof) && !(x[i] > hif);   // key in (lo, hi]
            cm |= ((unsigned)cnd) << i;
            cc += (int)cnd;
        }
        int incl = cc;                                   // intra-warp inclusive scan
        #pragma unroll
        for (int o = 1; o < 32; o <<= 1) {
            int n = __shfl_up_sync(0xFFFFFFFFu, incl, o);
            if (lane >= o) incl += n;
        }
        int wtot = __shfl_sync(0xFFFFFFFFu, incl, 31);
        if (lane == 0) s_part[wid] = (unsigned)wtot;
        __syncthreads();
        if (wid == 0 && lane < NWARP) {                  // scan warp totals -> bases
            int v = (int)s_part[lane];
            int inc = v;
            #pragma unroll
            for (int o = 1; o < NWARP; o <<= 1) {
                int n = __shfl_up_sync(0x0000FFFFu, inc, o);
                if (lane >= o) inc += n;
            }
            s_part[lane] = (unsigned)(inc - v);
        }
        __syncthreads();
        int ofs = (int)s_part[wid] + (incl - cc);
        #pragma unroll
        for (int i = 0; i < VPT; i++) {
            if ((cm >> i) & 1u) s_cand[ofs++] = x[i];
        }
        __syncthreads();

        // ---- phase 3: warp 0 finishes bisection on register candidates ----
        if (wid == 0) {
            const int m = (int)(c_lo - c_hi);
            float cd[VPT];
            #pragma unroll
            for (int j = 0; j < VPT; j++) {
                int p = lane + 32 * j;
                cd[j] = (p < m) ? s_cand[p] : __uint_as_float(0xFF800000u); // -inf pad
            }
            while ((hi - lo) > 1u) {
                unsigned mid = lo + ((hi - lo) >> 1);
                float piv = key_to_float(mid);
                unsigned c = 0;
                #pragma unroll
                for (int j = 0; j < VPT; j++) c += (cd[j] > piv) ? 1u : 0u;
                c = __reduce_add_sync(0xFFFFFFFFu, c) + c_hi;
                if (c <= (unsigned)idx) hi = mid; else lo = mid;
            }
            if (lane == 0) s_resf = key_to_float(hi);
        }
        __syncthreads();
        thresh = s_resf;
    }

    // ---- epilogue: exact reference arithmetic order ----
    const float t_r = mx - thresh;                 // max_in - thresh
    float acc = 0.0f;
    #pragma unroll
    for (int i = 0; i < VPT; i++) {
        float w  = fmaxf((x[i] + t_r) - mx, 0.0f); // relu(inputs + t_r - max)
        float we = w * __expf(x[i]);               // w_t * exp(inputs)
        x[i] = we;
        acc += we;
    }
    acc = warp_sum_f(acc);
    if (lane == 0) s_partf[wid] = acc;
    __syncthreads();
    if (wid == 0) {
        float v = (lane < NWARP) ? s_partf[lane] : 0.0f;
        v = warp_sum_f(v);
        if (lane == 0) s_resf = v;
    }
    __syncthreads();
    const float inv = 1.0f / s_resf;
    #pragma unroll
    for (int i = 0; i < 4; i++) {
        float4 v;
        v.x = x[4*i+0] * inv; v.y = x[4*i+1] * inv;
        v.z = x[4*i+2] * inv; v.w = x[4*i+3] * inv;
        op[t + i * THREADS] = v;
    }
}

extern "C" void kernel_launch(void* const* d_in, const int* in_sizes, int n_in,
                              void* d_out, int out_size) {
    const float* in   = (const float*)d_in[0];   // inputs [B, F] fp32
    const float* rate = (const float*)d_in[1];   // sparsity_rate [1] fp32
    float* out = (float*)d_out;
    const int rows = in_sizes[0] / FEAT;
    rsoftmax_kernel<<<rows, THREADS>>>(in, rate, out);
}

// round 7
// speedup vs baseline: 1.3754x; 1.3754x over previous
#include <cuda_runtime.h>
#include <cstdint>

#define THREADS 512
#define VPT 16
#define NWARP 16
#define FEAT 8192
#define CAP1 512
#define FULL 0xFFFFFFFFu

static_assert(THREADS * VPT == FEAT, "row must tile exactly");

// Monotonic uint key for fp32 (total order matching float order on finite data).
__device__ __forceinline__ unsigned f2k(float f) {
    unsigned u = __float_as_uint(f);
    return u ^ ((unsigned)((int)u >> 31) | 0x80000000u);
}
// Pivot decode; negative-NaN-zone keys squashed to -inf so float compares
// against the pivot stay monotone for all finite data.
__device__ __forceinline__ float key_to_float(unsigned k) {
    unsigned u = (k & 0x80000000u) ? (k ^ 0x80000000u) : ~k;
    float f = __uint_as_float(u);
    if (k < 0x007FFFFFu) f = __uint_as_float(0xFF800000u);  // -inf
    return f;
}

__global__ void __launch_bounds__(THREADS, 2)
rsoftmax_kernel(const float* __restrict__ in, const float* __restrict__ rate_p,
                float* __restrict__ out)
{
    __shared__ __align__(16) float    s_fmax[NWARP];
    __shared__ __align__(16) float    s_fmin[NWARP];
    __shared__ __align__(16) float    s_fsum[NWARP];
    __shared__ __align__(16) unsigned s_cnt[2][NWARP];   // double-buffered
    __shared__ __align__(16) unsigned s_wt[NWARP];
    __shared__ __align__(16) float    s_cand[CAP1];
    __shared__ __align__(16) float    s_esum[NWARP];
    __shared__ float s_thresh;

    const int t    = threadIdx.x;
    const int lane = t & 31;
    const int wid  = t >> 5;
    const size_t row = blockIdx.x;
    const float4* rp = reinterpret_cast<const float4*>(in + row * FEAT);
    float4*       op = reinterpret_cast<float4*>(out + row * FEAT);

    // rank index from device-resident trainable scalar
    float rate = __ldg(rate_p);
    rate = fminf(fmaxf(rate, 0.0f), 1.0f);
    int idx = (int)(rate * (float)FEAT);          // truncation == astype(int32)
    if (idx > FEAT - 1) idx = FEAT - 1;           // jnp.take clip mode

    // ---- load row (coalesced float4) ----
    float x[VPT];
    #pragma unroll
    for (int i = 0; i < 4; i++) {
        float4 v = __ldg(rp + t + i * THREADS);
        x[4*i+0] = v.x; x[4*i+1] = v.y; x[4*i+2] = v.z; x[4*i+3] = v.w;
    }

    // ---- fused max / min / sum, single barrier ----
    float mx = x[0], mn = x[0], sm = x[0];
    #pragma unroll
    for (int i = 1; i < VPT; i++) { mx = fmaxf(mx, x[i]); mn = fminf(mn, x[i]); sm += x[i]; }
    #pragma unroll
    for (int o = 16; o; o >>= 1) {
        mx = fmaxf(mx, __shfl_xor_sync(FULL, mx, o));
        mn = fminf(mn, __shfl_xor_sync(FULL, mn, o));
        sm += __shfl_xor_sync(FULL, sm, o);
    }
    if (lane == 0) { s_fmax[wid] = mx; s_fmin[wid] = mn; s_fsum[wid] = sm; }
    __syncthreads();
    {
        const float4* qa = (const float4*)s_fmax;
        const float4* qb = (const float4*)s_fmin;
        const float4* qc = (const float4*)s_fsum;
        float4 a0=qa[0],a1=qa[1],a2=qa[2],a3=qa[3];
        float4 b0=qb[0],b1=qb[1],b2=qb[2],b3=qb[3];
        float4 c0=qc[0],c1=qc[1],c2=qc[2],c3=qc[3];
        mx = fmaxf(fmaxf(fmaxf(a0.x,a0.y),fmaxf(a0.z,a0.w)),
             fmaxf(fmaxf(fmaxf(a1.x,a1.y),fmaxf(a1.z,a1.w)),
             fmaxf(fmaxf(fmaxf(a2.x,a2.y),fmaxf(a2.z,a2.w)),
                   fmaxf(fmaxf(a3.x,a3.y),fmaxf(a3.z,a3.w)))));
        mn = fminf(fminf(fminf(b0.x,b0.y),fminf(b0.z,b0.w)),
             fminf(fminf(fminf(b1.x,b1.y),fminf(b1.z,b1.w)),
             fminf(fminf(fminf(b2.x,b2.y),fminf(b2.z,b2.w)),
                   fminf(fminf(b3.x,b3.y),fminf(b3.z,b3.w)))));
        sm = ((c0.x+c0.y)+(c0.z+c0.w)) + ((c1.x+c1.y)+(c1.z+c1.w))
           + ((c2.x+c2.y)+(c2.z+c2.w)) + ((c3.x+c3.y)+(c3.z+c3.w));
    }

    // ---- phase 1: bracketed bisection, mean-key first pivot ----
    unsigned kmax = f2k(mx), kmin = f2k(mn);
    unsigned lo = kmin ? (kmin - 1u) : 0u;
    unsigned hi = kmax;
    unsigned c_lo = FEAT, c_hi = 0u;
    unsigned km = f2k(sm * (1.0f / (float)FEAT));
    int par = 0;
    bool first = true;
    while ((hi - lo) > 1u && (c_lo - c_hi) > CAP1) {
        unsigned mid = lo + ((hi - lo) >> 1);
        if (first) { first = false; if (km > lo && km < hi) mid = km; }
        float piv = key_to_float(mid);
        unsigned c = 0;
        #pragma unroll
        for (int i = 0; i < VPT; i++) c += (unsigned)(x[i] > piv);
        c = __reduce_add_sync(FULL, c);
        if (lane == 0) s_cnt[par][wid] = c;
        __syncthreads();
        const uint4* q = (const uint4*)s_cnt[par];
        uint4 a=q[0], b=q[1], d=q[2], e=q[3];
        c = (a.x+a.y+a.z+a.w) + (b.x+b.y+b.z+b.w)
          + (d.x+d.y+d.z+d.w) + (e.x+e.y+e.z+e.w);
        par ^= 1;
        if (c <= (unsigned)idx) { hi = mid; c_hi = c; }
        else                    { lo = mid; c_lo = c; }
    }

    float thresh;
    if ((hi - lo) <= 1u) {
        thresh = key_to_float(hi);            // uniform: every thread computes it
    } else {
        // ---- phase 2: compact <=512 candidates ----
        float lof = key_to_float(lo), hif = key_to_float(hi);
        unsigned cm = 0; int cc = 0;
        #pragma unroll
        for (int i = 0; i < VPT; i++) {
            bool cnd = (x[i] > lof) && !(x[i] > hif);   // key in (lo, hi]
            cm |= ((unsigned)cnd) << i; cc += (int)cnd;
        }
        int incl = cc;
        #pragma unroll
        for (int o = 1; o < 32; o <<= 1) {
            int n = __shfl_up_sync(FULL, incl, o);
            if (lane >= o) incl += n;
        }
        int wtot = __shfl_sync(FULL, incl, 31);
        if (lane == 0) s_wt[wid] = (unsigned)wtot;
        __syncthreads();
        unsigned base = 0;
        {
            const uint4* q = (const uint4*)s_wt;
            uint4 a=q[0], b=q[1], d=q[2], e=q[3];
            unsigned wt[16] = {a.x,a.y,a.z,a.w, b.x,b.y,b.z,b.w,
                               d.x,d.y,d.z,d.w, e.x,e.y,e.z,e.w};
            #pragma unroll
            for (int w = 0; w < 16; w++) base += (w < wid) ? wt[w] : 0u;
        }
        int ofs = (int)base + (incl - cc);
        #pragma unroll
        for (int i = 0; i < VPT; i++)
            if ((cm >> i) & 1u) s_cand[ofs++] = x[i];
        __syncthreads();

        // ---- phase 3 (warp 0): short bisection, then all-pairs rank select ----
        if (wid == 0) {
            const int m0 = (int)(c_lo - c_hi);
            // FIX: additive base for pivot counts must stay at the PHASE-2 c_hi.
            // The candidate set is fixed (elements in the phase-2 bracket), so
            // global_count(piv) = (#candidates > piv) + c_base, independent of
            // how the phase-3 bracket narrows. R4/R5 used the mutated c_hi here,
            // double-counting candidates above the shrinking hi -> wrong thresh.
            const unsigned c_base = c_hi;
            float cd[VPT];
            #pragma unroll
            for (int j = 0; j < VPT; j++) {
                int p = lane + 32 * j;
                cd[j] = (p < m0) ? s_cand[p] : __uint_as_float(0xFF800000u);
            }
            while ((hi - lo) > 1u && (c_lo - c_hi) > 32u) {
                unsigned mid = lo + ((hi - lo) >> 1);
                float piv = key_to_float(mid);
                unsigned c = 0;
                #pragma unroll
                for (int j = 0; j < VPT; j++) c += (unsigned)(cd[j] > piv);
                c = __reduce_add_sync(FULL, c) + c_base;   // <- fixed base
                if (c <= (unsigned)idx) { hi = mid; c_hi = c; }
                else                    { lo = mid; c_lo = c; }
            }
            float th;
            if ((hi - lo) <= 1u) {
                th = key_to_float(hi);
            } else {
                // compact the <=32 survivors to one per lane
                float lof2 = key_to_float(lo), hif2 = key_to_float(hi);
                unsigned cm2 = 0; int cc2 = 0;
                #pragma unroll
                for (int j = 0; j < VPT; j++) {
                    bool cn = (cd[j] > lof2) && !(cd[j] > hif2);
                    cm2 |= ((unsigned)cn) << j; cc2 += (int)cn;
                }
                int inc2 = cc2;
                #pragma unroll
                for (int o = 1; o < 32; o <<= 1) {
                    int n = __shfl_up_sync(FULL, inc2, o);
                    if (lane >= o) inc2 += n;
                }
                int ofs2 = inc2 - cc2;
                #pragma unroll
                for (int j = 0; j < VPT; j++)
                    if ((cm2 >> j) & 1u) s_cand[ofs2++] = cd[j];
                __syncwarp();
                const int m = (int)(c_lo - c_hi);            // <= 32 survivors
                const unsigned r = (unsigned)idx - c_hi;     // 0-indexed desc rank
                float v = (lane < m) ? s_cand[lane] : __uint_as_float(0xFF800000u);
                unsigned cgt = 0, ceq = 0;
                #pragma unroll
                for (int j = 0; j < 32; j++) {
                    float vj = __shfl_sync(FULL, v, j);
                    cgt += (unsigned)(vj > v);
                    ceq += (unsigned)(vj == v);
                }
                bool hit = (lane < m) && (cgt <= r) && (cgt + ceq > r);
                unsigned bal = __ballot_sync(FULL, hit);
                th = __shfl_sync(FULL, v, __ffs(bal) - 1);
            }
            if (lane == 0) s_thresh = th;
        }
        __syncthreads();
        thresh = s_thresh;
    }

    // ---- epilogue: exact reference arithmetic order ----
    const float t_r = mx - thresh;                   // max_in - thresh
    float acc = 0.0f;
    #pragma unroll
    for (int i = 0; i < VPT; i++) {
        float w  = fmaxf((x[i] + t_r) - mx, 0.0f);   // relu(inputs + t_r - max)
        float we = w * __expf(x[i]);                 // w_t * exp(inputs)
        x[i] = we;
        acc += we;
    }
    #pragma unroll
    for (int o = 16; o; o >>= 1) acc += __shfl_xor_sync(FULL, acc, o);
    if (lane == 0) s_esum[wid] = acc;
    __syncthreads();
    float s;
    {
        const float4* q = (const float4*)s_esum;
        float4 a=q[0], b=q[1], d=q[2], e=q[3];
        s = ((a.x+a.y)+(a.z+a.w)) + ((b.x+b.y)+(b.z+b.w))
          + ((d.x+d.y)+(d.z+d.w)) + ((e.x+e.y)+(e.z+e.w));
    }
    const float inv = 1.0f / s;
    #pragma unroll
    for (int i = 0; i < 4; i++) {
        float4 v;
        v.x = x[4*i+0] * inv; v.y = x[4*i+1] * inv;
        v.z = x[4*i+2] * inv; v.w = x[4*i+3] * inv;
        op[t + i * THREADS] = v;
    }
}

extern "C" void kernel_launch(void* const* d_in, const int* in_sizes, int n_in,
                              void* d_out, int out_size) {
    const float* in   = (const float*)d_in[0];   // inputs [B, F] fp32
    const float* rate = (const float*)d_in[1];   // sparsity_rate [1] fp32
    float* out = (float*)d_out;
    const int rows = in_sizes[0] / FEAT;
    rsoftmax_kernel<<<rows, THREADS>>>(in, rate, out);
}